// round 10
// baseline (speedup 1.0000x reference)
#include <cuda_runtime.h>
#include <cstdint>
#include <cstddef>

#define Bb   64
#define Nn   512
#define CINc 128
#define Hh   256
#define OUTd 12
#define Ee   8192
#define G3   768
#define BN   (Bb*Nn)

// ------------------------- device scratch (no allocs) -----------------------
__device__ float g_xwz[BN*Hh], g_xwh[BN*Hh], g_cz[BN*Hh], g_ch[BN*Hh];
__device__ float g_zlin[BN*Hh], g_hlin[BN*Hh];
__device__ float g_gi[(size_t)Nn*G3*Bb];
__device__ float g_h1[(size_t)Nn*Bb*Hh], g_h2[(size_t)Nn*Bb*Hh];
__device__ float g_deg[Nn], g_dinv[Nn], g_selfnorm[Nn];
__device__ int   g_cnt[Nn], g_rowptr[Nn+1], g_fillpos[Nn];
__device__ int   g_csr_src[Ee];
__device__ float g_csr_norm[Ee];
__device__ unsigned          g_bar_grp[16];
__device__ unsigned          g_bar_root;
__device__ volatile unsigned g_bar_gen;

// ------------------------- helpers ------------------------------------------
__device__ __forceinline__ float sigf(float x) { return 1.0f / (1.0f + expf(-x)); }

// two-level grid barrier across 128 co-resident blocks (16 groups x 8)
__device__ __forceinline__ void grid_barrier() {
    __syncthreads();
    if (threadIdx.x == 0) {
        unsigned gen = g_bar_gen;
        __threadfence();
        int grp = blockIdx.x & 15;
        bool rel = false;
        if (atomicAdd(&g_bar_grp[grp], 1u) == 7u) {
            atomicExch(&g_bar_grp[grp], 0u);
            __threadfence();
            if (atomicAdd(&g_bar_root, 1u) == 15u) {
                atomicExch(&g_bar_root, 0u);
                __threadfence();
                g_bar_gen = gen + 1u;
                rel = true;
            }
        }
        if (!rel) { while (g_bar_gen == gen) { __nanosleep(32); } }
        __threadfence();
    }
    __syncthreads();
}

// ------------------------- edge preprocessing -------------------------------
__global__ void prep_init() {
    int t = threadIdx.x;
    if (t < Nn) { g_deg[t] = 2.0f; g_cnt[t] = 0; }
}
__global__ void prep_count(const int* __restrict__ ei, const float* __restrict__ ew) {
    int e = blockIdx.x * 256 + threadIdx.x;
    if (e >= Ee) return;
    int tgt = ei[Ee + e];
    atomicAdd(&g_deg[tgt], ew[e]);
    atomicAdd(&g_cnt[tgt], 1);
}
__global__ void prep_scan() {
    __shared__ int s[Nn];
    int t = threadIdx.x;
    float d = g_deg[t];
    float di = (d > 0.f) ? rsqrtf(d) : 0.f;
    g_dinv[t] = di;
    g_selfnorm[t] = 2.0f * di * di;
    s[t] = g_cnt[t];
    __syncthreads();
    for (int off = 1; off < Nn; off <<= 1) {
        int v = (t >= off) ? s[t - off] : 0;
        __syncthreads();
        s[t] += v;
        __syncthreads();
    }
    g_rowptr[t + 1] = s[t];
    if (t == 0) g_rowptr[0] = 0;
    g_fillpos[t] = s[t] - g_cnt[t];
}
__global__ void prep_fill(const int* __restrict__ ei, const float* __restrict__ ew) {
    int e = blockIdx.x * 256 + threadIdx.x;
    if (e >= Ee) return;
    int src = ei[e], tgt = ei[Ee + e];
    int pos = atomicAdd(&g_fillpos[tgt], 1);
    g_csr_src[pos]  = src;
    g_csr_norm[pos] = g_dinv[src] * ew[e] * g_dinv[tgt];
}

// ------------------------- tiled SGEMM: C=A@B(+bias) ------------------------
__global__ void sgemm64(const float* __restrict__ A, const float* __restrict__ Bm,
                        const float* __restrict__ bias, float* __restrict__ C,
                        int M, int K, int Nc) {
    __shared__ __align__(16) float As[16][68];
    __shared__ __align__(16) float Bs[16][68];
    int m0 = blockIdx.x * 64, n0 = blockIdx.y * 64;
    int tid = threadIdx.x;
    int tx = tid & 15, ty = tid >> 4;
    float acc[4][4] = {};
    for (int k0 = 0; k0 < K; k0 += 16) {
        #pragma unroll
        for (int i = 0; i < 4; i++) {
            int idx = tid + i * 256;
            int m = idx >> 4, k = idx & 15;
            As[k][m] = A[(size_t)(m0 + m) * K + k0 + k];
        }
        #pragma unroll
        for (int i = 0; i < 4; i++) {
            int idx = tid + i * 256;
            int k = idx >> 6, n = idx & 63;
            Bs[k][n] = Bm[(size_t)(k0 + k) * Nc + n0 + n];
        }
        __syncthreads();
        #pragma unroll
        for (int k = 0; k < 16; k++) {
            float4 av = *(const float4*)&As[k][ty * 4];
            float4 bv = *(const float4*)&Bs[k][tx * 4];
            float a[4] = {av.x, av.y, av.z, av.w};
            float b[4] = {bv.x, bv.y, bv.z, bv.w};
            #pragma unroll
            for (int i = 0; i < 4; i++)
                #pragma unroll
                for (int j = 0; j < 4; j++)
                    acc[i][j] += a[i] * b[j];
        }
        __syncthreads();
    }
    float bj[4];
    #pragma unroll
    for (int j = 0; j < 4; j++) bj[j] = bias ? bias[n0 + tx * 4 + j] : 0.f;
    #pragma unroll
    for (int i = 0; i < 4; i++) {
        int m = m0 + ty * 4 + i;
        #pragma unroll
        for (int j = 0; j < 4; j++)
            C[(size_t)m * Nc + n0 + tx * 4 + j] = acc[i][j] + bj[j];
    }
}

// ------------------------- gi GEMM: GI[n][o][b] = X(b,n,:)@W[o,:]+bih[o] ----
__global__ void gi_gemm(const float* __restrict__ Xbase, int strideB, int strideN,
                        const float* __restrict__ W, const float* __restrict__ bih,
                        int K) {
    __shared__ __align__(16) float Xs[16][68];   // [k][b]
    __shared__ __align__(16) float Ws[16][68];   // [k][o]
    int n  = blockIdx.x;
    int o0 = blockIdx.y * 64;
    int tid = threadIdx.x;
    int tb = tid & 15, to = tid >> 4;
    float acc[4][4] = {};
    for (int k0 = 0; k0 < K; k0 += 16) {
        #pragma unroll
        for (int i = 0; i < 4; i++) {
            int idx = tid + i * 256;
            int b = idx >> 4, k = idx & 15;
            Xs[k][b] = Xbase[(size_t)b * strideB + (size_t)n * strideN + k0 + k];
        }
        #pragma unroll
        for (int i = 0; i < 4; i++) {
            int idx = tid + i * 256;
            int o = idx >> 4, k = idx & 15;
            Ws[k][o] = W[(size_t)(o0 + o) * K + k0 + k];
        }
        __syncthreads();
        #pragma unroll
        for (int k = 0; k < 16; k++) {
            float4 wv4 = *(const float4*)&Ws[k][to * 4];
            float4 xv4 = *(const float4*)&Xs[k][tb * 4];
            float wv[4] = {wv4.x, wv4.y, wv4.z, wv4.w};
            float xv[4] = {xv4.x, xv4.y, xv4.z, xv4.w};
            #pragma unroll
            for (int i = 0; i < 4; i++)
                #pragma unroll
                for (int j = 0; j < 4; j++)
                    acc[i][j] += wv[i] * xv[j];
        }
        __syncthreads();
    }
    size_t base = (size_t)n * G3 * Bb;
    #pragma unroll
    for (int i = 0; i < 4; i++) {
        int o = o0 + to * 4 + i;
        float bv = bih[o];
        #pragma unroll
        for (int j = 0; j < 4; j++)
            g_gi[base + (size_t)o * Bb + tb * 4 + j] = acc[i][j] + bv;
    }
}

// ------------------------- GCN aggregation (z & h gates) --------------------
__global__ void gcn_agg(const float* __restrict__ bz, const float* __restrict__ bh) {
    int t = blockIdx.x, b = blockIdx.y, c = threadIdx.x;
    size_t rowself = ((size_t)b * Nn + t) * Hh + c;
    float sn = g_selfnorm[t];
    float az = sn * g_xwz[rowself];
    float ah = sn * g_xwh[rowself];
    int e0 = g_rowptr[t], e1 = g_rowptr[t + 1];
    for (int e = e0; e < e1; e++) {
        int s = g_csr_src[e];
        float w = g_csr_norm[e];
        size_t ri = ((size_t)b * Nn + s) * Hh + c;
        az += w * g_xwz[ri];
        ah += w * g_xwh[ri];
    }
    g_cz[rowself] = az + bz[c];
    g_ch[rowself] = ah + bh[c];
}

// ------------------------- persistent GRU recurrence ------------------------
// 128 blocks (16 j-groups x 8 b-groups), 384 threads.
// Whh slice (48 rows x 256, pad 260) resident in smem for all 512 steps.
__global__ void __launch_bounds__(384, 1)
rec_kernel(const float* __restrict__ Whh, const float* __restrict__ bhh, int layer) {
    extern __shared__ float sm[];
    float* Whs = sm;                 // 48*260
    float* hs  = sm + 48 * 260;      // 8*260
    float* ghs = hs + 8 * 260;       // 384
    float* hbuf = layer ? g_h2 : g_h1;

    int tid = threadIdx.x;
    int jg = blockIdx.x >> 3, bg = blockIdx.x & 7;
    int j0 = jg * 16, b0 = bg * 8;
    int gate = tid >> 7, r = tid & 127, jl = r >> 3, bl = r & 7;
    int orow = gate * Hh + j0 + jl;

    for (int idx = tid; idx < 48 * 256; idx += 384) {
        int g = idx >> 8, k = idx & 255;
        int grow = (g >> 4) * Hh + j0 + (g & 15);
        Whs[g * 260 + k] = Whh[(size_t)grow * Hh + k];
    }
    float bhv = bhh[orow];
    const float4* wr4 = (const float4*)(Whs + (gate * 16 + jl) * 260);
    const float4* hr4 = (const float4*)(hs + bl * 260);

    for (int n = 0; n < Nn; n++) {
        if (n == 0) {
            for (int idx = tid; idx < 512; idx += 384) {
                int b = idx >> 6, k4 = idx & 63;
                ((float4*)(hs + b * 260))[k4] = make_float4(0.f, 0.f, 0.f, 0.f);
            }
        } else {
            const float4* src = (const float4*)hbuf;
            for (int idx = tid; idx < 512; idx += 384) {
                int b = idx >> 6, k4 = idx & 63;
                ((float4*)(hs + b * 260))[k4] =
                    src[(((size_t)(n - 1) * Bb + b0 + b) * Hh) / 4 + k4];
            }
        }
        __syncthreads();

        float4 a = make_float4(0.f, 0.f, 0.f, 0.f);
        #pragma unroll 8
        for (int k4 = 0; k4 < 64; k4++) {
            float4 w = wr4[k4];
            float4 h = hr4[k4];
            a.x += w.x * h.x; a.y += w.y * h.y;
            a.z += w.z * h.z; a.w += w.w * h.w;
        }
        float s = (a.x + a.y) + (a.z + a.w) + bhv;
        if (gate < 2) s += g_gi[((size_t)n * G3 + orow) * Bb + b0 + bl];
        ghs[gate * 128 + r] = s;
        __syncthreads();

        if (tid < 128) {
            float rr = sigf(ghs[tid]);
            float zz = sigf(ghs[128 + tid]);
            float gin = g_gi[((size_t)n * G3 + 2 * Hh + j0 + jl) * Bb + b0 + bl];
            float nn = tanhf(gin + rr * ghs[256 + tid]);
            float hp = hs[bl * 260 + j0 + jl];
            float hnew = (1.f - zz) * nn + zz * hp;
            hbuf[((size_t)n * Bb + b0 + bl) * Hh + j0 + jl] = hnew;
        }
        grid_barrier();
    }
}

// ------------------------- fused epilogue -----------------------------------
__global__ void epilogue(const float* __restrict__ l1W, const float* __restrict__ l1b,
                         const float* __restrict__ l2W, const float* __restrict__ l2b,
                         const float* __restrict__ l3W, const float* __restrict__ l3b,
                         float* __restrict__ out) {
    __shared__ float red1[8], red2[8];
    __shared__ float s1s, s2s;
    int n = blockIdx.x, b = blockIdx.y, c = threadIdx.x;
    size_t i = ((size_t)b * Nn + n) * Hh + c;
    float z  = sigf(g_zlin[i]);
    float ht = tanhf(g_hlin[i]);
    float v1 = fmaxf((1.f - z) * ht, 0.f) * l1W[c];
    float v2 = g_h2[((size_t)n * Bb + b) * Hh + c] * l2W[c];
    #pragma unroll
    for (int o = 16; o; o >>= 1) {
        v1 += __shfl_down_sync(0xffffffffu, v1, o);
        v2 += __shfl_down_sync(0xffffffffu, v2, o);
    }
    if ((c & 31) == 0) { red1[c >> 5] = v1; red2[c >> 5] = v2; }
    __syncthreads();
    if (c == 0) {
        float a = 0.f, bsum = 0.f;
        #pragma unroll
        for (int k = 0; k < 8; k++) { a += red1[k]; bsum += red2[k]; }
        s1s = a + l1b[0];
        s2s = bsum + l2b[0];
    }
    __syncthreads();
    if (c < OUTd)
        out[((size_t)b * Nn + n) * OUTd + c] =
            s2s * l3W[c] + s1s * l3W[OUTd + c] + l3b[c];
}

// ------------------------- launch -------------------------------------------
extern "C" void kernel_launch(void* const* d_in, const int* in_sizes, int n_in,
                              void* d_out, int out_size) {
    const float* x    = (const float*)d_in[0];
    const int*   ei   = (const int*)d_in[1];
    const float* ew   = (const float*)d_in[2];
    const float* Wz   = (const float*)d_in[3];
    const float* bz   = (const float*)d_in[4];
    const float* lzW  = (const float*)d_in[5];
    const float* lzb  = (const float*)d_in[6];
    // d_in[7..10] (R gate) are algebraically dead since H0 = 0
    const float* Wh   = (const float*)d_in[11];
    const float* bh   = (const float*)d_in[12];
    const float* lhW  = (const float*)d_in[13];
    const float* lhb  = (const float*)d_in[14];
    const float* Wih0 = (const float*)d_in[15];
    const float* Whh0 = (const float*)d_in[16];
    const float* bih0 = (const float*)d_in[17];
    const float* bhh0 = (const float*)d_in[18];
    const float* Wih1 = (const float*)d_in[19];
    const float* Whh1 = (const float*)d_in[20];
    const float* bih1 = (const float*)d_in[21];
    const float* bhh1 = (const float*)d_in[22];
    const float* l1W  = (const float*)d_in[23];
    const float* l1b  = (const float*)d_in[24];
    const float* l2W  = (const float*)d_in[25];
    const float* l2b  = (const float*)d_in[26];
    const float* l3W  = (const float*)d_in[27];
    const float* l3b  = (const float*)d_in[28];
    float* out = (float*)d_out;

    float *xwz, *xwh, *cz, *ch, *zlin, *hlin, *h1;
    cudaGetSymbolAddress((void**)&xwz,  g_xwz);
    cudaGetSymbolAddress((void**)&xwh,  g_xwh);
    cudaGetSymbolAddress((void**)&cz,   g_cz);
    cudaGetSymbolAddress((void**)&ch,   g_ch);
    cudaGetSymbolAddress((void**)&zlin, g_zlin);
    cudaGetSymbolAddress((void**)&hlin, g_hlin);
    cudaGetSymbolAddress((void**)&h1,   g_h1);

    const int REC_SMEM = (48 * 260 + 8 * 260 + 384) * 4;   // 59776 B
    cudaFuncSetAttribute(rec_kernel, cudaFuncAttributeMaxDynamicSharedMemorySize,
                         REC_SMEM);

    // edge preprocessing
    prep_init<<<1, 512>>>();
    prep_count<<<(Ee + 255) / 256, 256>>>(ei, ew);
    prep_scan<<<1, Nn>>>();
    prep_fill<<<(Ee + 255) / 256, 256>>>(ei, ew);

    // GCN branch
    dim3 g1(BN / 64, Hh / 64);
    sgemm64<<<g1, 256>>>(x, Wz, nullptr, xwz, BN, CINc, Hh);
    sgemm64<<<g1, 256>>>(x, Wh, nullptr, xwh, BN, CINc, Hh);
    dim3 g2(Nn, Bb);
    gcn_agg<<<g2, 256>>>(bz, bh);
    sgemm64<<<g1, 256>>>(cz, lzW, lzb, zlin, BN, Hh, Hh);   // top H rows of lzW
    sgemm64<<<g1, 256>>>(ch, lhW, lhb, hlin, BN, Hh, Hh);   // top H rows of lhW

    // GRU branch
    dim3 g3(Nn, G3 / 64);
    gi_gemm<<<g3, 256>>>(x, Nn * CINc, CINc, Wih0, bih0, CINc);
    rec_kernel<<<128, 384, REC_SMEM>>>(Whh0, bhh0, 0);
    gi_gemm<<<g3, 256>>>(h1, Hh, Bb * Hh, Wih1, bih1, Hh);
    rec_kernel<<<128, 384, REC_SMEM>>>(Whh1, bhh1, 1);

    // heads + output
    epilogue<<<g2, 256>>>(l1W, l1b, l2W, l2b, l3W, l3b, out);
}

// round 12
// speedup vs baseline: 1.6037x; 1.6037x over previous
#include <cuda_runtime.h>
#include <cstdint>
#include <cstddef>

#define Bb   64
#define Nn   512
#define CINc 128
#define Hh   256
#define OUTd 12
#define Ee   8192
#define G3   768
#define BN   (Bb*Nn)

// ------------------------- device scratch (no allocs) -----------------------
__device__ float g_xwz[BN*Hh], g_xwh[BN*Hh], g_cz[BN*Hh], g_ch[BN*Hh];
__device__ float g_zlin[BN*Hh], g_hlin[BN*Hh];
__device__ float g_gi[(size_t)Nn*G3*Bb];
__device__ float g_h1[(size_t)Nn*Bb*Hh], g_h2[(size_t)Nn*Bb*Hh];
__device__ float g_deg[Nn], g_dinv[Nn], g_selfnorm[Nn];
__device__ int   g_cnt[Nn], g_rowptr[Nn+1], g_fillpos[Nn];
__device__ int   g_csr_src[Ee];
__device__ float g_csr_norm[Ee];

// ------------------------- helpers ------------------------------------------
__device__ __forceinline__ float sigf(float x) { return 1.0f / (1.0f + expf(-x)); }

__device__ __forceinline__ uint32_t smem_u32(const void* p) {
    uint32_t a;
    asm("{ .reg .u64 t; cvta.to.shared.u64 t, %1; cvt.u32.u64 %0, t; }"
        : "=r"(a) : "l"(p));
    return a;
}
__device__ __forceinline__ uint32_t ctarank() {
    uint32_t r;
    asm("mov.u32 %0, %%cluster_ctarank;" : "=r"(r));
    return r;
}
__device__ __forceinline__ void st_cluster_f32(uint32_t local_addr, int peer, float v) {
    uint32_t ra;
    asm volatile("mapa.shared::cluster.u32 %0, %1, %2;" : "=r"(ra) : "r"(local_addr), "r"(peer));
    asm volatile("st.shared::cluster.f32 [%0], %1;" :: "r"(ra), "f"(v) : "memory");
}
__device__ __forceinline__ void cluster_sync_() {
    asm volatile("barrier.cluster.arrive.aligned;" ::: "memory");
    asm volatile("barrier.cluster.wait.aligned;" ::: "memory");
}

// ------------------------- edge preprocessing -------------------------------
__global__ void prep_init() {
    int t = threadIdx.x;
    if (t < Nn) { g_deg[t] = 2.0f; g_cnt[t] = 0; }
}
__global__ void prep_count(const int* __restrict__ ei, const float* __restrict__ ew) {
    int e = blockIdx.x * 256 + threadIdx.x;
    if (e >= Ee) return;
    int tgt = ei[Ee + e];
    atomicAdd(&g_deg[tgt], ew[e]);
    atomicAdd(&g_cnt[tgt], 1);
}
__global__ void prep_scan() {
    __shared__ int s[Nn];
    int t = threadIdx.x;
    float d = g_deg[t];
    float di = (d > 0.f) ? rsqrtf(d) : 0.f;
    g_dinv[t] = di;
    g_selfnorm[t] = 2.0f * di * di;
    s[t] = g_cnt[t];
    __syncthreads();
    for (int off = 1; off < Nn; off <<= 1) {
        int v = (t >= off) ? s[t - off] : 0;
        __syncthreads();
        s[t] += v;
        __syncthreads();
    }
    g_rowptr[t + 1] = s[t];
    if (t == 0) g_rowptr[0] = 0;
    g_fillpos[t] = s[t] - g_cnt[t];
}
__global__ void prep_fill(const int* __restrict__ ei, const float* __restrict__ ew) {
    int e = blockIdx.x * 256 + threadIdx.x;
    if (e >= Ee) return;
    int src = ei[e], tgt = ei[Ee + e];
    int pos = atomicAdd(&g_fillpos[tgt], 1);
    g_csr_src[pos]  = src;
    g_csr_norm[pos] = g_dinv[src] * ew[e] * g_dinv[tgt];
}

// ------------------------- tiled SGEMM: C=A@B(+bias) ------------------------
__global__ void sgemm64(const float* __restrict__ A, const float* __restrict__ Bm,
                        const float* __restrict__ bias, float* __restrict__ C,
                        int M, int K, int Nc) {
    __shared__ __align__(16) float As[16][68];
    __shared__ __align__(16) float Bs[16][68];
    int m0 = blockIdx.x * 64, n0 = blockIdx.y * 64;
    int tid = threadIdx.x;
    int tx = tid & 15, ty = tid >> 4;
    float acc[4][4] = {};
    for (int k0 = 0; k0 < K; k0 += 16) {
        #pragma unroll
        for (int i = 0; i < 4; i++) {
            int idx = tid + i * 256;
            int m = idx >> 4, k = idx & 15;
            As[k][m] = A[(size_t)(m0 + m) * K + k0 + k];
        }
        #pragma unroll
        for (int i = 0; i < 4; i++) {
            int idx = tid + i * 256;
            int k = idx >> 6, n = idx & 63;
            Bs[k][n] = Bm[(size_t)(k0 + k) * Nc + n0 + n];
        }
        __syncthreads();
        #pragma unroll
        for (int k = 0; k < 16; k++) {
            float4 av = *(const float4*)&As[k][ty * 4];
            float4 bv = *(const float4*)&Bs[k][tx * 4];
            float a[4] = {av.x, av.y, av.z, av.w};
            float b[4] = {bv.x, bv.y, bv.z, bv.w};
            #pragma unroll
            for (int i = 0; i < 4; i++)
                #pragma unroll
                for (int j = 0; j < 4; j++)
                    acc[i][j] += a[i] * b[j];
        }
        __syncthreads();
    }
    float bj[4];
    #pragma unroll
    for (int j = 0; j < 4; j++) bj[j] = bias ? bias[n0 + tx * 4 + j] : 0.f;
    #pragma unroll
    for (int i = 0; i < 4; i++) {
        int m = m0 + ty * 4 + i;
        #pragma unroll
        for (int j = 0; j < 4; j++)
            C[(size_t)m * Nc + n0 + tx * 4 + j] = acc[i][j] + bj[j];
    }
}

// ------------------------- gi GEMM: GI[n][o][b] = X(b,n,:)@W[o,:]+bih[o] ----
__global__ void gi_gemm(const float* __restrict__ Xbase, int strideB, int strideN,
                        const float* __restrict__ W, const float* __restrict__ bih,
                        int K) {
    __shared__ __align__(16) float Xs[16][68];
    __shared__ __align__(16) float Ws[16][68];
    int n  = blockIdx.x;
    int o0 = blockIdx.y * 64;
    int tid = threadIdx.x;
    int tb = tid & 15, to = tid >> 4;
    float acc[4][4] = {};
    for (int k0 = 0; k0 < K; k0 += 16) {
        #pragma unroll
        for (int i = 0; i < 4; i++) {
            int idx = tid + i * 256;
            int b = idx >> 4, k = idx & 15;
            Xs[k][b] = Xbase[(size_t)b * strideB + (size_t)n * strideN + k0 + k];
        }
        #pragma unroll
        for (int i = 0; i < 4; i++) {
            int idx = tid + i * 256;
            int o = idx >> 4, k = idx & 15;
            Ws[k][o] = W[(size_t)(o0 + o) * K + k0 + k];
        }
        __syncthreads();
        #pragma unroll
        for (int k = 0; k < 16; k++) {
            float4 wv4 = *(const float4*)&Ws[k][to * 4];
            float4 xv4 = *(const float4*)&Xs[k][tb * 4];
            float wv[4] = {wv4.x, wv4.y, wv4.z, wv4.w};
            float xv[4] = {xv4.x, xv4.y, xv4.z, xv4.w};
            #pragma unroll
            for (int i = 0; i < 4; i++)
                #pragma unroll
                for (int j = 0; j < 4; j++)
                    acc[i][j] += wv[i] * xv[j];
        }
        __syncthreads();
    }
    size_t base = (size_t)n * G3 * Bb;
    #pragma unroll
    for (int i = 0; i < 4; i++) {
        int o = o0 + to * 4 + i;
        float bv = bih[o];
        #pragma unroll
        for (int j = 0; j < 4; j++)
            g_gi[base + (size_t)o * Bb + tb * 4 + j] = acc[i][j] + bv;
    }
}

// ------------------------- GCN aggregation (z & h gates) --------------------
__global__ void gcn_agg(const float* __restrict__ bz, const float* __restrict__ bh) {
    int t = blockIdx.x, b = blockIdx.y, c = threadIdx.x;
    size_t rowself = ((size_t)b * Nn + t) * Hh + c;
    float sn = g_selfnorm[t];
    float az = sn * g_xwz[rowself];
    float ah = sn * g_xwh[rowself];
    int e0 = g_rowptr[t], e1 = g_rowptr[t + 1];
    for (int e = e0; e < e1; e++) {
        int s = g_csr_src[e];
        float w = g_csr_norm[e];
        size_t ri = ((size_t)b * Nn + s) * Hh + c;
        az += w * g_xwz[ri];
        ah += w * g_xwh[ri];
    }
    g_cz[rowself] = az + bz[c];
    g_ch[rowself] = ah + bh[c];
}

// ------------------------- cluster GRU recurrence ---------------------------
// 128 CTAs = 16 clusters x 8. Cluster c owns batches [4c, 4c+4).
// CTA rank r owns j-slice [32r, 32r+32) of H for all 3 gates:
//   96 Whh rows (97.5 KB) resident in smem for all 512 steps.
// Per step: dots -> gate combine -> broadcast 128 new h values to all 8
// peers' smem (st.shared::cluster), one cluster.sync. Double-buffered h.
__global__ void __launch_bounds__(384, 1) __cluster_dims__(8, 1, 1)
rec_cluster(const float* __restrict__ Whh, const float* __restrict__ bhh, int layer) {
    extern __shared__ __align__(16) float sm[];
    float* Whs = sm;                         // 96 x 260
    float* hb0 = sm + 96 * 260;              // 4 x 260
    float* hb1 = hb0 + 4 * 260;              // 4 x 260
    float* ghs = hb1 + 4 * 260;              // 384
    float* hbuf = layer ? g_h2 : g_h1;

    int tid = threadIdx.x;
    uint32_t rank = ctarank();
    int cluster_id = blockIdx.x >> 3;
    int b0 = cluster_id * 4;                 // 4 batches per cluster

    int g  = tid >> 7;                       // gate 0=r,1=z,2=n
    int rm = tid & 127;
    int jl = rm >> 2;                        // 0..31
    int bl = rm & 3;                         // 0..3
    int orow = g * Hh + rank * 32 + jl;      // global gate row

    // load Whh slice: local row L = g*32+jl  <->  global row g*256+rank*32+jl
    for (int idx = tid; idx < 96 * 64; idx += 384) {   // float4 granularity
        int L = idx >> 6, k4 = idx & 63;
        int grow = (L >> 5) * Hh + rank * 32 + (L & 31);
        ((float4*)(Whs + L * 260))[k4] =
            ((const float4*)(Whh + (size_t)grow * Hh))[k4];
    }
    // zero read buffer for step 0
    for (int idx = tid; idx < 4 * 260; idx += 384) hb0[idx] = 0.f;
    float bhv = bhh[orow];
    const float4* wr4 = (const float4*)(Whs + (g * 32 + jl) * 260);

    uint32_t hb0_u = smem_u32(hb0), hb1_u = smem_u32(hb1);
    __syncthreads();
    cluster_sync_();   // peers' smem initialized before any remote write

    for (int n = 0; n < Nn; n++) {
        const float* hread = (n & 1) ? hb1 : hb0;
        uint32_t hw_u = (n & 1) ? hb0_u : hb1_u;

        // prefetch gi (overlaps with the dot below)
        size_t gibase = (size_t)n * G3 * Bb;
        float gival = (g < 2)
            ? g_gi[gibase + (size_t)orow * Bb + b0 + bl] : 0.f;
        float gin_pref = 0.f;
        if (tid < 128)
            gin_pref = g_gi[gibase + (size_t)(2 * Hh + rank * 32 + jl) * Bb + b0 + bl];

        // 256-dot: Whh[row] . h[bl]
        const float4* hr4 = (const float4*)(hread + bl * 260);
        float4 a = make_float4(0.f, 0.f, 0.f, 0.f);
        #pragma unroll 8
        for (int k4 = 0; k4 < 64; k4++) {
            float4 w = wr4[k4];
            float4 h = hr4[k4];
            a.x += w.x * h.x; a.y += w.y * h.y;
            a.z += w.z * h.z; a.w += w.w * h.w;
        }
        ghs[g * 128 + rm] = (a.x + a.y) + (a.z + a.w) + bhv + gival;
        __syncthreads();

        if (tid < 128) {
            float rr = sigf(ghs[tid]);
            float zz = sigf(ghs[128 + tid]);
            float nn = tanhf(gin_pref + rr * ghs[256 + tid]);
            float hp = hread[bl * 260 + rank * 32 + jl];
            float hnew = (1.f - zz) * nn + zz * hp;
            // broadcast into every cluster CTA's write buffer (incl. self)
            uint32_t off = hw_u + (uint32_t)(bl * 260 + rank * 32 + jl) * 4u;
            #pragma unroll
            for (int p = 0; p < 8; p++) st_cluster_f32(off, p, hnew);
            // publish to global for next layer / epilogue
            hbuf[((size_t)n * Bb + b0 + bl) * Hh + rank * 32 + jl] = hnew;
        }
        cluster_sync_();
    }
}

// ------------------------- fused epilogue -----------------------------------
__global__ void epilogue(const float* __restrict__ l1W, const float* __restrict__ l1b,
                         const float* __restrict__ l2W, const float* __restrict__ l2b,
                         const float* __restrict__ l3W, const float* __restrict__ l3b,
                         float* __restrict__ out) {
    __shared__ float red1[8], red2[8];
    __shared__ float s1s, s2s;
    int n = blockIdx.x, b = blockIdx.y, c = threadIdx.x;
    size_t i = ((size_t)b * Nn + n) * Hh + c;
    float z  = sigf(g_zlin[i]);
    float ht = tanhf(g_hlin[i]);
    float v1 = fmaxf((1.f - z) * ht, 0.f) * l1W[c];
    float v2 = g_h2[((size_t)n * Bb + b) * Hh + c] * l2W[c];
    #pragma unroll
    for (int o = 16; o; o >>= 1) {
        v1 += __shfl_down_sync(0xffffffffu, v1, o);
        v2 += __shfl_down_sync(0xffffffffu, v2, o);
    }
    if ((c & 31) == 0) { red1[c >> 5] = v1; red2[c >> 5] = v2; }
    __syncthreads();
    if (c == 0) {
        float a = 0.f, bs = 0.f;
        #pragma unroll
        for (int k = 0; k < 8; k++) { a += red1[k]; bs += red2[k]; }
        s1s = a + l1b[0];
        s2s = bs + l2b[0];
    }
    __syncthreads();
    if (c < OUTd)
        out[((size_t)b * Nn + n) * OUTd + c] =
            s2s * l3W[c] + s1s * l3W[OUTd + c] + l3b[c];
}

// ------------------------- launch -------------------------------------------
extern "C" void kernel_launch(void* const* d_in, const int* in_sizes, int n_in,
                              void* d_out, int out_size) {
    const float* x    = (const float*)d_in[0];
    const int*   ei   = (const int*)d_in[1];
    const float* ew   = (const float*)d_in[2];
    const float* Wz   = (const float*)d_in[3];
    const float* bz   = (const float*)d_in[4];
    const float* lzW  = (const float*)d_in[5];
    const float* lzb  = (const float*)d_in[6];
    // d_in[7..10] (R gate) algebraically dead since H0 = 0
    const float* Wh   = (const float*)d_in[11];
    const float* bh   = (const float*)d_in[12];
    const float* lhW  = (const float*)d_in[13];
    const float* lhb  = (const float*)d_in[14];
    const float* Wih0 = (const float*)d_in[15];
    const float* Whh0 = (const float*)d_in[16];
    const float* bih0 = (const float*)d_in[17];
    // d_in[18] bhh0 used below
    const float* bhh0 = (const float*)d_in[18];
    const float* Wih1 = (const float*)d_in[19];
    const float* Whh1 = (const float*)d_in[20];
    const float* bih1 = (const float*)d_in[21];
    const float* bhh1 = (const float*)d_in[22];
    const float* l1W  = (const float*)d_in[23];
    const float* l1b  = (const float*)d_in[24];
    const float* l2W  = (const float*)d_in[25];
    const float* l2b  = (const float*)d_in[26];
    const float* l3W  = (const float*)d_in[27];
    const float* l3b  = (const float*)d_in[28];
    float* out = (float*)d_out;

    float *xwz, *xwh, *cz, *ch, *zlin, *hlin, *h1;
    cudaGetSymbolAddress((void**)&xwz,  g_xwz);
    cudaGetSymbolAddress((void**)&xwh,  g_xwh);
    cudaGetSymbolAddress((void**)&cz,   g_cz);
    cudaGetSymbolAddress((void**)&ch,   g_ch);
    cudaGetSymbolAddress((void**)&zlin, g_zlin);
    cudaGetSymbolAddress((void**)&hlin, g_hlin);
    cudaGetSymbolAddress((void**)&h1,   g_h1);

    const int REC_SMEM = (96 * 260 + 8 * 260 + 384) * 4;   // 109,696 B
    cudaFuncSetAttribute(rec_cluster, cudaFuncAttributeMaxDynamicSharedMemorySize,
                         REC_SMEM);

    // edge preprocessing
    prep_init<<<1, 512>>>();
    prep_count<<<(Ee + 255) / 256, 256>>>(ei, ew);
    prep_scan<<<1, Nn>>>();
    prep_fill<<<(Ee + 255) / 256, 256>>>(ei, ew);

    // GCN branch
    dim3 g1(BN / 64, Hh / 64);
    sgemm64<<<g1, 256>>>(x, Wz, nullptr, xwz, BN, CINc, Hh);
    sgemm64<<<g1, 256>>>(x, Wh, nullptr, xwh, BN, CINc, Hh);
    dim3 g2(Nn, Bb);
    gcn_agg<<<g2, 256>>>(bz, bh);
    sgemm64<<<g1, 256>>>(cz, lzW, lzb, zlin, BN, Hh, Hh);   // top H rows of lzW
    sgemm64<<<g1, 256>>>(ch, lhW, lhb, hlin, BN, Hh, Hh);   // top H rows of lhW

    // GRU branch
    dim3 g3(Nn, G3 / 64);
    gi_gemm<<<g3, 256>>>(x, Nn * CINc, CINc, Wih0, bih0, CINc);
    rec_cluster<<<128, 384, REC_SMEM>>>(Whh0, bhh0, 0);
    gi_gemm<<<g3, 256>>>(h1, Hh, Bb * Hh, Wih1, bih1, Hh);
    rec_cluster<<<128, 384, REC_SMEM>>>(Whh1, bhh1, 1);

    // heads + output
    epilogue<<<g2, 256>>>(l1W, l1b, l2W, l2b, l3W, l3b, out);
}

// round 14
// speedup vs baseline: 1.7079x; 1.0649x over previous
#include <cuda_runtime.h>
#include <cstdint>
#include <cstddef>

#define Bb   64
#define Nn   512
#define CINc 128
#define Hh   256
#define OUTd 12
#define Ee   8192
#define G3   768
#define BN   (Bb*Nn)

// ------------------------- device scratch (no allocs) -----------------------
__device__ float g_xwz[BN*Hh], g_xwh[BN*Hh], g_cz[BN*Hh], g_ch[BN*Hh];
__device__ float g_zlin[BN*Hh], g_hlin[BN*Hh];
__device__ float g_gi[(size_t)Nn*G3*Bb];
__device__ float g_h1[(size_t)Nn*Bb*Hh], g_h2[(size_t)Nn*Bb*Hh];
__device__ float g_deg[Nn], g_dinv[Nn], g_selfnorm[Nn];
__device__ int   g_cnt[Nn], g_rowptr[Nn+1], g_fillpos[Nn];
__device__ int   g_csr_src[Ee];
__device__ float g_csr_norm[Ee];

// ------------------------- helpers ------------------------------------------
__device__ __forceinline__ float sigf(float x) { return 1.0f / (1.0f + expf(-x)); }

__device__ __forceinline__ uint32_t smem_u32(const void* p) {
    uint32_t a;
    asm("{ .reg .u64 t; cvta.to.shared.u64 t, %1; cvt.u32.u64 %0, t; }"
        : "=r"(a) : "l"(p));
    return a;
}
__device__ __forceinline__ uint32_t ctarank() {
    uint32_t r;
    asm("mov.u32 %0, %%cluster_ctarank;" : "=r"(r));
    return r;
}
__device__ __forceinline__ void st_cluster_f32(uint32_t local_addr, int peer, float v) {
    uint32_t ra;
    asm volatile("mapa.shared::cluster.u32 %0, %1, %2;" : "=r"(ra) : "r"(local_addr), "r"(peer));
    asm volatile("st.shared::cluster.f32 [%0], %1;" :: "r"(ra), "f"(v) : "memory");
}
__device__ __forceinline__ void cluster_arrive_() {
    asm volatile("barrier.cluster.arrive.aligned;" ::: "memory");
}
__device__ __forceinline__ void cluster_wait_() {
    asm volatile("barrier.cluster.wait.aligned;" ::: "memory");
}

// ------------------------- edge preprocessing -------------------------------
__global__ void prep_init() {
    int t = threadIdx.x;
    if (t < Nn) { g_deg[t] = 2.0f; g_cnt[t] = 0; }
}
__global__ void prep_count(const int* __restrict__ ei, const float* __restrict__ ew) {
    int e = blockIdx.x * 256 + threadIdx.x;
    if (e >= Ee) return;
    int tgt = ei[Ee + e];
    atomicAdd(&g_deg[tgt], ew[e]);
    atomicAdd(&g_cnt[tgt], 1);
}
__global__ void prep_scan() {
    __shared__ int s[Nn];
    int t = threadIdx.x;
    float d = g_deg[t];
    float di = (d > 0.f) ? rsqrtf(d) : 0.f;
    g_dinv[t] = di;
    g_selfnorm[t] = 2.0f * di * di;
    s[t] = g_cnt[t];
    __syncthreads();
    for (int off = 1; off < Nn; off <<= 1) {
        int v = (t >= off) ? s[t - off] : 0;
        __syncthreads();
        s[t] += v;
        __syncthreads();
    }
    g_rowptr[t + 1] = s[t];
    if (t == 0) g_rowptr[0] = 0;
    g_fillpos[t] = s[t] - g_cnt[t];
}
__global__ void prep_fill(const int* __restrict__ ei, const float* __restrict__ ew) {
    int e = blockIdx.x * 256 + threadIdx.x;
    if (e >= Ee) return;
    int src = ei[e], tgt = ei[Ee + e];
    int pos = atomicAdd(&g_fillpos[tgt], 1);
    g_csr_src[pos]  = src;
    g_csr_norm[pos] = g_dinv[src] * ew[e] * g_dinv[tgt];
}

// ------------------------- tiled SGEMM: C=A@B(+bias) ------------------------
__global__ void sgemm64(const float* __restrict__ A, const float* __restrict__ Bm,
                        const float* __restrict__ bias, float* __restrict__ C,
                        int M, int K, int Nc) {
    __shared__ __align__(16) float As[16][68];
    __shared__ __align__(16) float Bs[16][68];
    int m0 = blockIdx.x * 64, n0 = blockIdx.y * 64;
    int tid = threadIdx.x;
    int tx = tid & 15, ty = tid >> 4;
    float acc[4][4] = {};
    for (int k0 = 0; k0 < K; k0 += 16) {
        #pragma unroll
        for (int i = 0; i < 4; i++) {
            int idx = tid + i * 256;
            int m = idx >> 4, k = idx & 15;
            As[k][m] = A[(size_t)(m0 + m) * K + k0 + k];
        }
        #pragma unroll
        for (int i = 0; i < 4; i++) {
            int idx = tid + i * 256;
            int k = idx >> 6, n = idx & 63;
            Bs[k][n] = Bm[(size_t)(k0 + k) * Nc + n0 + n];
        }
        __syncthreads();
        #pragma unroll
        for (int k = 0; k < 16; k++) {
            float4 av = *(const float4*)&As[k][ty * 4];
            float4 bv = *(const float4*)&Bs[k][tx * 4];
            float a[4] = {av.x, av.y, av.z, av.w};
            float b[4] = {bv.x, bv.y, bv.z, bv.w};
            #pragma unroll
            for (int i = 0; i < 4; i++)
                #pragma unroll
                for (int j = 0; j < 4; j++)
                    acc[i][j] += a[i] * b[j];
        }
        __syncthreads();
    }
    float bj[4];
    #pragma unroll
    for (int j = 0; j < 4; j++) bj[j] = bias ? bias[n0 + tx * 4 + j] : 0.f;
    #pragma unroll
    for (int i = 0; i < 4; i++) {
        int m = m0 + ty * 4 + i;
        #pragma unroll
        for (int j = 0; j < 4; j++)
            C[(size_t)m * Nc + n0 + tx * 4 + j] = acc[i][j] + bj[j];
    }
}

// ------------------------- gi GEMM: GI[n][o][b] = X(b,n,:)@W[o,:]+bih[o] ----
__global__ void gi_gemm(const float* __restrict__ Xbase, int strideB, int strideN,
                        const float* __restrict__ W, const float* __restrict__ bih,
                        int K) {
    __shared__ __align__(16) float Xs[16][68];
    __shared__ __align__(16) float Ws[16][68];
    int n  = blockIdx.x;
    int o0 = blockIdx.y * 64;
    int tid = threadIdx.x;
    int tb = tid & 15, to = tid >> 4;
    float acc[4][4] = {};
    for (int k0 = 0; k0 < K; k0 += 16) {
        #pragma unroll
        for (int i = 0; i < 4; i++) {
            int idx = tid + i * 256;
            int b = idx >> 4, k = idx & 15;
            Xs[k][b] = Xbase[(size_t)b * strideB + (size_t)n * strideN + k0 + k];
        }
        #pragma unroll
        for (int i = 0; i < 4; i++) {
            int idx = tid + i * 256;
            int o = idx >> 4, k = idx & 15;
            Ws[k][o] = W[(size_t)(o0 + o) * K + k0 + k];
        }
        __syncthreads();
        #pragma unroll
        for (int k = 0; k < 16; k++) {
            float4 wv4 = *(const float4*)&Ws[k][to * 4];
            float4 xv4 = *(const float4*)&Xs[k][tb * 4];
            float wv[4] = {wv4.x, wv4.y, wv4.z, wv4.w};
            float xv[4] = {xv4.x, xv4.y, xv4.z, xv4.w};
            #pragma unroll
            for (int i = 0; i < 4; i++)
                #pragma unroll
                for (int j = 0; j < 4; j++)
                    acc[i][j] += wv[i] * xv[j];
        }
        __syncthreads();
    }
    size_t base = (size_t)n * G3 * Bb;
    #pragma unroll
    for (int i = 0; i < 4; i++) {
        int o = o0 + to * 4 + i;
        float bv = bih[o];
        #pragma unroll
        for (int j = 0; j < 4; j++)
            g_gi[base + (size_t)o * Bb + tb * 4 + j] = acc[i][j] + bv;
    }
}

// ------------------------- GCN aggregation (z & h gates) --------------------
__global__ void gcn_agg(const float* __restrict__ bz, const float* __restrict__ bh) {
    int t = blockIdx.x, b = blockIdx.y, c = threadIdx.x;
    size_t rowself = ((size_t)b * Nn + t) * Hh + c;
    float sn = g_selfnorm[t];
    float az = sn * g_xwz[rowself];
    float ah = sn * g_xwh[rowself];
    int e0 = g_rowptr[t], e1 = g_rowptr[t + 1];
    for (int e = e0; e < e1; e++) {
        int s = g_csr_src[e];
        float w = g_csr_norm[e];
        size_t ri = ((size_t)b * Nn + s) * Hh + c;
        az += w * g_xwz[ri];
        ah += w * g_xwh[ri];
    }
    g_cz[rowself] = az + bz[c];
    g_ch[rowself] = ah + bh[c];
}

// ------------------------- cluster GRU recurrence ---------------------------
// 128 CTAs = 16 clusters x 8. Cluster c owns batches [4c, 4c+4).
// CTA rank r owns j-slice [32r, 32r+32) of H for all 3 gates.
// Split barrier per step: remote stores -> arrive -> (publish + gi prefetch
// for n+1, hiding L2 latency and barrier propagation) -> wait.
__global__ void __launch_bounds__(384, 1) __cluster_dims__(8, 1, 1)
rec_cluster(const float* __restrict__ Whh, const float* __restrict__ bhh, int layer) {
    extern __shared__ __align__(16) float sm[];
    float* Whs = sm;                         // 96 x 260
    float* hb0 = sm + 96 * 260;              // 4 x 260
    float* hb1 = hb0 + 4 * 260;              // 4 x 260
    float* ghs = hb1 + 4 * 260;              // 384
    float* hbuf = layer ? g_h2 : g_h1;

    int tid = threadIdx.x;
    uint32_t rank = ctarank();
    int cluster_id = blockIdx.x >> 3;
    int b0 = cluster_id * 4;                 // 4 batches per cluster

    int g  = tid >> 7;                       // gate 0=r,1=z,2=n
    int rm = tid & 127;
    int jl = rm >> 2;                        // 0..31
    int bl = rm & 3;                         // 0..3
    int orow = g * Hh + rank * 32 + jl;      // global gate row

    // load Whh slice: local row L = g*32+jl  <->  global row g*256+rank*32+jl
    for (int idx = tid; idx < 96 * 64; idx += 384) {
        int L = idx >> 6, k4 = idx & 63;
        int grow = (L >> 5) * Hh + rank * 32 + (L & 31);
        ((float4*)(Whs + L * 260))[k4] =
            ((const float4*)(Whh + (size_t)grow * Hh))[k4];
    }
    for (int idx = tid; idx < 4 * 260; idx += 384) hb0[idx] = 0.f;
    float bhv = bhh[orow];
    const float4* wr4 = (const float4*)(Whs + (g * 32 + jl) * 260);

    uint32_t hb0_u = smem_u32(hb0), hb1_u = smem_u32(hb1);

    // prefetch gi for step 0
    size_t gi_r  = (size_t)orow * Bb + b0 + bl;                      // gates r/z
    size_t gi_n  = (size_t)(2 * Hh + rank * 32 + jl) * Bb + b0 + bl; // gate n
    float gv = (g < 2)    ? g_gi[gi_r] : 0.f;
    float gn = (tid < 128) ? g_gi[gi_n] : 0.f;

    __syncthreads();
    cluster_arrive_();
    cluster_wait_();   // peers' smem initialized before any remote write

    for (int n = 0; n < Nn; n++) {
        const float* hread = (n & 1) ? hb1 : hb0;
        uint32_t hw_u = (n & 1) ? hb0_u : hb1_u;

        // 256-dot: Whh[row] . h[bl]
        const float4* hr4 = (const float4*)(hread + bl * 260);
        float4 a = make_float4(0.f, 0.f, 0.f, 0.f);
        #pragma unroll 8
        for (int k4 = 0; k4 < 64; k4++) {
            float4 w = wr4[k4];
            float4 h = hr4[k4];
            a.x += w.x * h.x; a.y += w.y * h.y;
            a.z += w.z * h.z; a.w += w.w * h.w;
        }
        ghs[g * 128 + rm] = (a.x + a.y) + (a.z + a.w) + bhv + gv;
        __syncthreads();

        float hnew = 0.f;
        if (tid < 128) {
            float rr = sigf(ghs[tid]);
            float zz = sigf(ghs[128 + tid]);
            float nn = tanhf(gn + rr * ghs[256 + tid]);
            float hp = hread[bl * 260 + rank * 32 + jl];
            hnew = (1.f - zz) * nn + zz * hp;
            uint32_t off = hw_u + (uint32_t)(bl * 260 + rank * 32 + jl) * 4u;
            #pragma unroll
            for (int p = 0; p < 8; p++) st_cluster_f32(off, p, hnew);
        }
        cluster_arrive_();

        // overlapped with barrier propagation: publish + next-step gi prefetch
        if (tid < 128)
            hbuf[((size_t)n * Bb + b0 + bl) * Hh + rank * 32 + jl] = hnew;
        int np = (n + 1 < Nn) ? n + 1 : n;
        size_t gib = (size_t)np * G3 * Bb;
        gv = (g < 2)    ? g_gi[gib + gi_r] : 0.f;
        gn = (tid < 128) ? g_gi[gib + gi_n] : 0.f;

        cluster_wait_();
    }
}

// ------------------------- fused epilogue -----------------------------------
__global__ void epilogue(const float* __restrict__ l1W, const float* __restrict__ l1b,
                         const float* __restrict__ l2W, const float* __restrict__ l2b,
                         const float* __restrict__ l3W, const float* __restrict__ l3b,
                         float* __restrict__ out) {
    __shared__ float red1[8], red2[8];
    __shared__ float s1s, s2s;
    int n = blockIdx.x, b = blockIdx.y, c = threadIdx.x;
    size_t i = ((size_t)b * Nn + n) * Hh + c;
    float z  = sigf(g_zlin[i]);
    float ht = tanhf(g_hlin[i]);
    float v1 = fmaxf((1.f - z) * ht, 0.f) * l1W[c];
    float v2 = g_h2[((size_t)n * Bb + b) * Hh + c] * l2W[c];
    #pragma unroll
    for (int o = 16; o; o >>= 1) {
        v1 += __shfl_down_sync(0xffffffffu, v1, o);
        v2 += __shfl_down_sync(0xffffffffu, v2, o);
    }
    if ((c & 31) == 0) { red1[c >> 5] = v1; red2[c >> 5] = v2; }
    __syncthreads();
    if (c == 0) {
        float a = 0.f, bs = 0.f;
        #pragma unroll
        for (int k = 0; k < 8; k++) { a += red1[k]; bs += red2[k]; }
        s1s = a + l1b[0];
        s2s = bs + l2b[0];
    }
    __syncthreads();
    if (c < OUTd)
        out[((size_t)b * Nn + n) * OUTd + c] =
            s2s * l3W[c] + s1s * l3W[OUTd + c] + l3b[c];
}

// ------------------------- launch -------------------------------------------
extern "C" void kernel_launch(void* const* d_in, const int* in_sizes, int n_in,
                              void* d_out, int out_size) {
    const float* x    = (const float*)d_in[0];
    const int*   ei   = (const int*)d_in[1];
    const float* ew   = (const float*)d_in[2];
    const float* Wz   = (const float*)d_in[3];
    const float* bz   = (const float*)d_in[4];
    const float* lzW  = (const float*)d_in[5];
    const float* lzb  = (const float*)d_in[6];
    // d_in[7..10] (R gate) algebraically dead since H0 = 0
    const float* Wh   = (const float*)d_in[11];
    const float* bh   = (const float*)d_in[12];
    const float* lhW  = (const float*)d_in[13];
    const float* lhb  = (const float*)d_in[14];
    const float* Wih0 = (const float*)d_in[15];
    const float* Whh0 = (const float*)d_in[16];
    const float* bih0 = (const float*)d_in[17];
    const float* bhh0 = (const float*)d_in[18];
    const float* Wih1 = (const float*)d_in[19];
    const float* Whh1 = (const float*)d_in[20];
    const float* bih1 = (const float*)d_in[21];
    const float* bhh1 = (const float*)d_in[22];
    const float* l1W  = (const float*)d_in[23];
    const float* l1b  = (const float*)d_in[24];
    const float* l2W  = (const float*)d_in[25];
    const float* l2b  = (const float*)d_in[26];
    const float* l3W  = (const float*)d_in[27];
    const float* l3b  = (const float*)d_in[28];
    float* out = (float*)d_out;

    float *xwz, *xwh, *cz, *ch, *zlin, *hlin, *h1;
    cudaGetSymbolAddress((void**)&xwz,  g_xwz);
    cudaGetSymbolAddress((void**)&xwh,  g_xwh);
    cudaGetSymbolAddress((void**)&cz,   g_cz);
    cudaGetSymbolAddress((void**)&ch,   g_ch);
    cudaGetSymbolAddress((void**)&zlin, g_zlin);
    cudaGetSymbolAddress((void**)&hlin, g_hlin);
    cudaGetSymbolAddress((void**)&h1,   g_h1);

    const int REC_SMEM = (96 * 260 + 8 * 260 + 384) * 4;   // 109,696 B
    cudaFuncSetAttribute(rec_cluster, cudaFuncAttributeMaxDynamicSharedMemorySize,
                         REC_SMEM);

    // one-time side stream + fork/join events (created on the uncaptured
    // correctness call; reused identically on every call -> deterministic)
    static cudaStream_t s2 = nullptr;
    static cudaEvent_t evFork = nullptr, evJoin = nullptr;
    if (s2 == nullptr) {
        cudaStreamCreateWithFlags(&s2, cudaStreamNonBlocking);
        cudaEventCreateWithFlags(&evFork, cudaEventDisableTiming);
        cudaEventCreateWithFlags(&evJoin, cudaEventDisableTiming);
    }

    // fork: GCN branch on s2, GRU branch on the main stream
    cudaEventRecord(evFork, 0);
    cudaStreamWaitEvent(s2, evFork, 0);

    // --- GCN branch (s2) ---
    prep_init<<<1, 512, 0, s2>>>();
    prep_count<<<(Ee + 255) / 256, 256, 0, s2>>>(ei, ew);
    prep_scan<<<1, Nn, 0, s2>>>();
    prep_fill<<<(Ee + 255) / 256, 256, 0, s2>>>(ei, ew);
    dim3 g1(BN / 64, Hh / 64);
    sgemm64<<<g1, 256, 0, s2>>>(x, Wz, nullptr, xwz, BN, CINc, Hh);
    sgemm64<<<g1, 256, 0, s2>>>(x, Wh, nullptr, xwh, BN, CINc, Hh);
    dim3 g2(Nn, Bb);
    gcn_agg<<<g2, 256, 0, s2>>>(bz, bh);
    sgemm64<<<g1, 256, 0, s2>>>(cz, lzW, lzb, zlin, BN, Hh, Hh);
    sgemm64<<<g1, 256, 0, s2>>>(ch, lhW, lhb, hlin, BN, Hh, Hh);
    cudaEventRecord(evJoin, s2);

    // --- GRU branch (main stream) ---
    dim3 g3(Nn, G3 / 64);
    gi_gemm<<<g3, 256>>>(x, Nn * CINc, CINc, Wih0, bih0, CINc);
    rec_cluster<<<128, 384, REC_SMEM>>>(Whh0, bhh0, 0);
    gi_gemm<<<g3, 256>>>(h1, Hh, Bb * Hh, Wih1, bih1, Hh);
    rec_cluster<<<128, 384, REC_SMEM>>>(Whh1, bhh1, 1);

    // join + epilogue
    cudaStreamWaitEvent(0, evJoin, 0);
    epilogue<<<g2, 256>>>(l1W, l1b, l2W, l2b, l3W, l3b, out);
}